// round 2
// baseline (speedup 1.0000x reference)
#include <cuda_runtime.h>

// Problem shape (fixed by reference setup_inputs)
#define BB 16
#define HH 256
#define WW 256
#define CC 128

#define THRESH_PRED 0.3f
#define THRESH_TRUE 0.5f
#define PENALTY_WEIGHT 0.05f

// Scratch bboxes: [mask(pred=0,true=1)][batch][ymin, xmin, ymax, xmax]
__device__ int g_box[2][BB][4];

// ---------------------------------------------------------------------------
// Kernel 0: reset scratch (graph-replay determinism: must re-init every call)
// ---------------------------------------------------------------------------
__global__ void bbox_init_kernel() {
    int i = threadIdx.x;              // 2*16*4 = 128 entries
    if (i < 2 * BB * 4) {
        int coord = i & 3;            // 0,1 = mins ; 2,3 = maxes
        ((int*)g_box)[i] = (coord < 2) ? HH : -1;
    }
}

// ---------------------------------------------------------------------------
// Kernel 1: streaming mask + bbox reduction.
// One warp per pixel: each lane loads one float4 (4 channels) from each
// tensor -> per-lane max -> ballot vote against threshold.
// Block = 1024 threads = 32 pixels (all within one batch: 65536 px/batch).
// ---------------------------------------------------------------------------
__global__ __launch_bounds__(1024, 2)
void bbox_mask_kernel(const float4* __restrict__ pred,
                      const float4* __restrict__ expo) {
    __shared__ int s_box[2][4];

    const int tid = threadIdx.x;
    if (tid < 8) {
        ((int*)s_box)[tid] = ((tid & 3) < 2) ? HH : -1;
    }
    __syncthreads();

    const int warp = tid >> 5;
    const int lane = tid & 31;

    // global pixel index for this warp
    const long long p = (long long)blockIdx.x * 32 + warp;
    const long long vbase = p * (CC / 4) + lane;   // float4 index

    const float4 a = pred[vbase];
    const float4 b = expo[vbase];

    const float pm = fmaxf(fmaxf(a.x, a.y), fmaxf(a.z, a.w));
    const float tm = fmaxf(fmaxf(b.x, b.y), fmaxf(b.z, b.w));

    const bool ptrue = __any_sync(0xffffffffu, pm > THRESH_PRED);
    const bool ttrue = __any_sync(0xffffffffu, tm > THRESH_TRUE);

    if (lane == 0) {
        const int y = (int)((p >> 8) & (HH - 1));  // (p / W) % H, W = 256
        const int x = (int)(p & (WW - 1));         // p % W
        if (ptrue) {
            atomicMin(&s_box[0][0], y);
            atomicMin(&s_box[0][1], x);
            atomicMax(&s_box[0][2], y);
            atomicMax(&s_box[0][3], x);
        }
        if (ttrue) {
            atomicMin(&s_box[1][0], y);
            atomicMin(&s_box[1][1], x);
            atomicMax(&s_box[1][2], y);
            atomicMax(&s_box[1][3], x);
        }
    }
    __syncthreads();

    if (tid < 8) {
        const int m = tid >> 2;
        const int c = tid & 3;
        const int batch = blockIdx.x >> 11;    // 2048 blocks per batch
        const int v = s_box[m][c];
        if (c < 2) {
            if (v < HH) atomicMin(&g_box[m][batch][c], v);
        } else {
            if (v >= 0) atomicMax(&g_box[m][batch][c], v);
        }
    }
}

// ---------------------------------------------------------------------------
// Kernel 2: penalty math + mean (single warp)
// ---------------------------------------------------------------------------
__global__ void bbox_final_kernel(float* __restrict__ out) {
    const int b = threadIdx.x;
    float pen = 0.0f;

    if (b < BB) {
        float py0, px0, py1, px1;
        float ty0, tx0, ty1, tx1;

        if (g_box[0][b][2] < 0) {                 // empty pred mask
            py0 = 0.0f; px0 = 0.0f; py1 = 1.0f; px1 = 1.0f;
        } else {
            py0 = (float)g_box[0][b][0];
            px0 = (float)g_box[0][b][1];
            py1 = (float)g_box[0][b][2];
            px1 = (float)g_box[0][b][3];
        }
        if (g_box[1][b][2] < 0) {                 // empty true mask
            ty0 = 0.0f; tx0 = 0.0f; ty1 = 1.0f; tx1 = 1.0f;
        } else {
            ty0 = (float)g_box[1][b][0];
            tx0 = (float)g_box[1][b][1];
            ty1 = (float)g_box[1][b][2];
            tx1 = (float)g_box[1][b][3];
        }

        const float pred_area = (py1 - py0 + 1.0f) * (px1 - px0 + 1.0f);
        const float true_area = (ty1 - ty0 + 1.0f) * (tx1 - tx0 + 1.0f);
        const float area_penalty =
            fmaxf(pred_area - true_area, 0.0f) / (true_area + 1.0f);

        const float dy = (py0 + py1) * 0.5f - (ty0 + ty1) * 0.5f;
        const float dx = (px0 + px1) * 0.5f - (tx0 + tx1) * 0.5f;
        const float center_offset = sqrtf(dy * dy + dx * dx) * (1.0f / 20.0f);

        pen = area_penalty + center_offset;
    }

    // warp sum over 32 lanes (upper 16 contribute 0)
    #pragma unroll
    for (int o = 16; o > 0; o >>= 1)
        pen += __shfl_down_sync(0xffffffffu, pen, o);

    if (b == 0)
        out[0] = PENALTY_WEIGHT * pen * (1.0f / (float)BB);
}

// ---------------------------------------------------------------------------
extern "C" void kernel_launch(void* const* d_in, const int* in_sizes, int n_in,
                              void* d_out, int out_size) {
    const float4* pred = (const float4*)d_in[0];   // prediction_probs
    const float4* expo = (const float4*)d_in[1];   // expected_onehot
    float* out = (float*)d_out;

    bbox_init_kernel<<<1, 128>>>();

    const int n_pixels = BB * HH * WW;             // 1,048,576
    const int blocks = n_pixels / 32;              // 32,768 blocks of 1024 thr
    bbox_mask_kernel<<<blocks, 1024>>>(pred, expo);

    bbox_final_kernel<<<1, 32>>>(out);
}

// round 3
// speedup vs baseline: 4.1812x; 4.1812x over previous
#include <cuda_runtime.h>

// Problem shape (fixed by reference setup_inputs)
#define BB 16
#define HH 256
#define WW 256
#define CC 128
#define C4 (CC / 4)          // 32 float4 per pixel

#define THRESH_PRED 0.3f
#define THRESH_TRUE 0.5f
#define PENALTY_WEIGHT 0.05f

// Scratch bboxes: [mask(pred=0,true=1)][batch][ymin, xmin, ymax, xmax]
// Statically initialized to sentinels; the final kernel RESETS it after
// reading, so every launch (and every graph replay) starts identical.
#define SENT_INIT {HH, WW, -1, -1}
#define SENT_B  SENT_INIT, SENT_INIT, SENT_INIT, SENT_INIT, \
                SENT_INIT, SENT_INIT, SENT_INIT, SENT_INIT, \
                SENT_INIT, SENT_INIT, SENT_INIT, SENT_INIT, \
                SENT_INIT, SENT_INIT, SENT_INIT, SENT_INIT
__device__ int g_box[2][BB][4] = { { SENT_B }, { SENT_B } };

__device__ __forceinline__ float max4(float4 v) {
    return fmaxf(fmaxf(v.x, v.y), fmaxf(v.z, v.w));
}

// ---------------------------------------------------------------------------
// Kernel 1: short-circuit mask + bbox reduction.
// One THREAD per pixel. First touch = channels [0,8) = one 32B sector per
// tensor. Fallback scan of channels [8,128) only when the first 8 are all
// below threshold (prob ~6.6e-5 / ~0.4% per tensor on this data, but the
// short-circuit is EXACT for any data: the mask predicate is monotone).
// Warp = 32 consecutive x in one row -> ballot gives x-range directly.
// ---------------------------------------------------------------------------
__global__ __launch_bounds__(1024, 2)
void bbox_mask_kernel(const float4* __restrict__ pred,
                      const float4* __restrict__ expo) {
    __shared__ int s_box[2][4];

    const int tid  = threadIdx.x;
    const int warp = tid >> 5;
    const int lane = tid & 31;

    if (tid < 8) ((int*)s_box)[tid] = ((tid & 3) < 2) ? HH : -1;
    __syncthreads();

    const int p = blockIdx.x * 1024 + tid;        // global pixel index
    const size_t base = (size_t)p * C4;           // float4 index of channel 0

    // First touch: channels 0..7 (32 bytes, one sector) from each tensor.
    const float4 a0 = pred[base + 0];
    const float4 a1 = pred[base + 1];
    const float4 b0 = expo[base + 0];
    const float4 b1 = expo[base + 1];

    bool pset = fmaxf(max4(a0), max4(a1)) > THRESH_PRED;
    bool tset = fmaxf(max4(b0), max4(b1)) > THRESH_TRUE;

    // Rare fallback: scan remaining channels until predicate resolves.
    if (!pset) {
        #pragma unroll 4
        for (int i = 2; i < C4; i++) {
            if (max4(pred[base + i]) > THRESH_PRED) { pset = true; break; }
        }
    }
    if (!tset) {
        #pragma unroll 4
        for (int i = 2; i < C4; i++) {
            if (max4(expo[base + i]) > THRESH_TRUE) { tset = true; break; }
        }
    }

    // Warp bbox: all 32 lanes share one row y; x = xb + lane.
    const unsigned pm = __ballot_sync(0xffffffffu, pset);
    const unsigned tm = __ballot_sync(0xffffffffu, tset);

    if (lane == 0 && (pm | tm)) {
        const int wbase = blockIdx.x * 1024 + warp * 32;
        const int y  = (wbase >> 8) & (HH - 1);
        const int xb = wbase & (WW - 32);         // multiple of 32 within row
        if (pm) {
            atomicMin(&s_box[0][0], y);
            atomicMax(&s_box[0][2], y);
            atomicMin(&s_box[0][1], xb + (__ffs(pm) - 1));
            atomicMax(&s_box[0][3], xb + (31 - __clz(pm)));
        }
        if (tm) {
            atomicMin(&s_box[1][0], y);
            atomicMax(&s_box[1][2], y);
            atomicMin(&s_box[1][1], xb + (__ffs(tm) - 1));
            atomicMax(&s_box[1][3], xb + (31 - __clz(tm)));
        }
    }
    __syncthreads();

    if (tid < 8) {
        const int m = tid >> 2;
        const int c = tid & 3;
        const int batch = blockIdx.x >> 6;        // 64 blocks per batch
        const int v = s_box[m][c];
        if (c < 2) {
            if (v < HH) atomicMin(&g_box[m][batch][c], v);
        } else {
            if (v >= 0) atomicMax(&g_box[m][batch][c], v);
        }
    }
}

// ---------------------------------------------------------------------------
// Kernel 2: penalty math + mean, then RESET g_box for the next replay.
// ---------------------------------------------------------------------------
__global__ void bbox_final_kernel(float* __restrict__ out) {
    const int tid = threadIdx.x;
    float pen = 0.0f;

    if (tid < BB) {
        const int b = tid;
        float py0, px0, py1, px1;
        float ty0, tx0, ty1, tx1;

        if (g_box[0][b][2] < 0) {                 // empty pred mask
            py0 = 0.0f; px0 = 0.0f; py1 = 1.0f; px1 = 1.0f;
        } else {
            py0 = (float)g_box[0][b][0];
            px0 = (float)g_box[0][b][1];
            py1 = (float)g_box[0][b][2];
            px1 = (float)g_box[0][b][3];
        }
        if (g_box[1][b][2] < 0) {                 // empty true mask
            ty0 = 0.0f; tx0 = 0.0f; ty1 = 1.0f; tx1 = 1.0f;
        } else {
            ty0 = (float)g_box[1][b][0];
            tx0 = (float)g_box[1][b][1];
            ty1 = (float)g_box[1][b][2];
            tx1 = (float)g_box[1][b][3];
        }

        const float pred_area = (py1 - py0 + 1.0f) * (px1 - px0 + 1.0f);
        const float true_area = (ty1 - ty0 + 1.0f) * (tx1 - tx0 + 1.0f);
        const float area_penalty =
            fmaxf(pred_area - true_area, 0.0f) / (true_area + 1.0f);

        const float dy = (py0 + py1) * 0.5f - (ty0 + ty1) * 0.5f;
        const float dx = (px0 + px1) * 0.5f - (tx0 + tx1) * 0.5f;
        const float center_offset = sqrtf(dy * dy + dx * dx) * (1.0f / 20.0f);

        pen = area_penalty + center_offset;
    }

    // warp 0 sums the 16 penalties
    if (tid < 32) {
        #pragma unroll
        for (int o = 16; o > 0; o >>= 1)
            pen += __shfl_down_sync(0xffffffffu, pen, o);
        if (tid == 0)
            out[0] = PENALTY_WEIGHT * pen * (1.0f / (float)BB);
    }

    __syncthreads();
    // Reset scratch to sentinels for the next graph replay.
    if (tid < 2 * BB * 4) {
        ((int*)g_box)[tid] = ((tid & 3) < 2) ? HH : -1;
    }
}

// ---------------------------------------------------------------------------
extern "C" void kernel_launch(void* const* d_in, const int* in_sizes, int n_in,
                              void* d_out, int out_size) {
    const float4* pred = (const float4*)d_in[0];   // prediction_probs
    const float4* expo = (const float4*)d_in[1];   // expected_onehot
    float* out = (float*)d_out;

    const int n_pixels = BB * HH * WW;             // 1,048,576
    bbox_mask_kernel<<<n_pixels / 1024, 1024>>>(pred, expo);
    bbox_final_kernel<<<1, 128>>>(out);
}

// round 4
// speedup vs baseline: 18.9016x; 4.5206x over previous
#include <cuda_runtime.h>

// Problem shape (fixed by reference setup_inputs)
#define BB 16
#define HH 256
#define WW 256
#define CC 128
#define C4 (CC / 4)          // 32 float4 per pixel

#define THRESH_PRED 0.3f
#define THRESH_TRUE 0.5f
#define PENALTY_WEIGHT 0.05f

__device__ float    g_pen[BB];
__device__ unsigned g_count = 0;     // reset by the last block every run

__device__ __forceinline__ float max4(float4 v) {
    return fmaxf(fmaxf(v.x, v.y), fmaxf(v.z, v.w));
}

// Scan channels [start*4, 128) until predicate resolves. Exact: the mask
// predicate max(ch) > T is monotone in the set of examined channels.
__device__ __forceinline__ bool scan_rest(const float4* __restrict__ p,
                                          size_t base, float T, int start) {
    for (int i = start; i < C4; i++) {
        if (max4(p[base + i]) > T) return true;
    }
    return false;
}

// ---------------------------------------------------------------------------
// One block per batch. 1024 threads = the 4 borders (256 px each).
// Fast path: if every border of a mask has >=1 set pixel, bbox is exactly
// [0,0,255,255]. Otherwise fall back to a full short-circuit scan of the
// batch (never triggers on this data; kept exact for arbitrary inputs).
// Last-finished block reduces the 16 penalties in fixed order.
// ---------------------------------------------------------------------------
__global__ __launch_bounds__(1024, 1)
void bbox_kernel(const float4* __restrict__ pred,
                 const float4* __restrict__ expo,
                 float* __restrict__ out) {
    __shared__ int s_flags[2];          // bit s set => border side s has a pixel
    __shared__ int s_box[2][4];         // fallback bbox (sentinels)

    const int b    = blockIdx.x;
    const int tid  = threadIdx.x;
    const int lane = tid & 31;

    if (tid < 2) s_flags[tid] = 0;
    if (tid < 8) ((int*)s_box)[tid] = ((tid & 3) < 2) ? HH : -1;
    __syncthreads();

    // --- Border pixel for this thread ---
    // side 0: row 0      (y=0,   x=j)
    // side 1: row 255    (y=255, x=j)
    // side 2: col 0      (y=j,   x=0)
    // side 3: col 255    (y=j,   x=255)
    const int side = tid >> 8;
    const int j    = tid & 255;
    const int y = (side == 0) ? 0 : (side == 1) ? (HH - 1) : j;
    const int x = (side == 2) ? 0 : (side == 3) ? (WW - 1) : j;

    const size_t base = ((size_t)b * (HH * WW) + (size_t)y * WW + x) * C4;

    // First touch: channels 0..7 from each tensor (4 independent LDG.128).
    const float4 a0 = pred[base + 0];
    const float4 a1 = pred[base + 1];
    const float4 e0 = expo[base + 0];
    const float4 e1 = expo[base + 1];

    bool pset = fmaxf(max4(a0), max4(a1)) > THRESH_PRED;
    bool tset = fmaxf(max4(e0), max4(e1)) > THRESH_TRUE;
    if (!pset) pset = scan_rest(pred, base, THRESH_PRED, 2);
    if (!tset) tset = scan_rest(expo, base, THRESH_TRUE, 2);

    // Each warp covers 32 pixels of one side (side = warp>>3).
    const unsigned pm = __ballot_sync(0xffffffffu, pset);
    const unsigned tm = __ballot_sync(0xffffffffu, tset);
    if (lane == 0) {
        const int bit = 1 << side;
        if (pm) atomicOr(&s_flags[0], bit);
        if (tm) atomicOr(&s_flags[1], bit);
    }
    __syncthreads();

    // --- Exact fallback: full-batch scan for any unresolved mask ---
    #pragma unroll
    for (int m = 0; m < 2; m++) {
        if (s_flags[m] != 0xF) {
            const float4* ptr = (m == 0) ? pred : expo;
            const float  T   = (m == 0) ? THRESH_PRED : THRESH_TRUE;
            for (int t = 0; t < (HH * WW) / 1024; t++) {
                const int idx = t * 1024 + tid;          // pixel within batch
                const size_t pb = ((size_t)b * (HH * WW) + idx) * C4;
                bool set = (fmaxf(max4(ptr[pb]), max4(ptr[pb + 1])) > T);
                if (!set) set = scan_rest(ptr, pb, T, 2);
                const unsigned mk = __ballot_sync(0xffffffffu, set);
                if (lane == 0 && mk) {
                    const int yy = idx >> 8;             // W = 256
                    const int xb = idx & (WW - 32);
                    atomicMin(&s_box[m][0], yy);
                    atomicMax(&s_box[m][2], yy);
                    atomicMin(&s_box[m][1], xb + (__ffs(mk) - 1));
                    atomicMax(&s_box[m][3], xb + (31 - __clz(mk)));
                }
            }
            __syncthreads();
        }
    }

    // --- Thread 0: penalty for this batch, then last-block final reduce ---
    if (tid == 0) {
        float bx[2][4];
        #pragma unroll
        for (int m = 0; m < 2; m++) {
            if (s_flags[m] == 0xF) {                      // borders resolved
                bx[m][0] = 0.0f; bx[m][1] = 0.0f;
                bx[m][2] = (float)(HH - 1); bx[m][3] = (float)(WW - 1);
            } else if (s_box[m][2] < 0) {                 // empty mask
                bx[m][0] = 0.0f; bx[m][1] = 0.0f;
                bx[m][2] = 1.0f; bx[m][3] = 1.0f;
            } else {                                      // fallback bbox
                bx[m][0] = (float)s_box[m][0];
                bx[m][1] = (float)s_box[m][1];
                bx[m][2] = (float)s_box[m][2];
                bx[m][3] = (float)s_box[m][3];
            }
        }

        const float pred_area = (bx[0][2] - bx[0][0] + 1.0f) * (bx[0][3] - bx[0][1] + 1.0f);
        const float true_area = (bx[1][2] - bx[1][0] + 1.0f) * (bx[1][3] - bx[1][1] + 1.0f);
        const float area_penalty =
            fmaxf(pred_area - true_area, 0.0f) / (true_area + 1.0f);

        const float dy = (bx[0][0] + bx[0][2]) * 0.5f - (bx[1][0] + bx[1][2]) * 0.5f;
        const float dx = (bx[0][1] + bx[0][3]) * 0.5f - (bx[1][1] + bx[1][3]) * 0.5f;
        const float center_offset = sqrtf(dy * dy + dx * dx) * (1.0f / 20.0f);

        g_pen[b] = area_penalty + center_offset;

        __threadfence();
        const unsigned old = atomicAdd(&g_count, 1u);
        if (old == BB - 1) {                              // I'm the last block
            __threadfence();
            float s = 0.0f;
            #pragma unroll
            for (int i = 0; i < BB; i++) s += g_pen[i];   // fixed order
            out[0] = PENALTY_WEIGHT * s * (1.0f / (float)BB);
            g_count = 0;                                  // reset for replay
        }
    }
}

// ---------------------------------------------------------------------------
extern "C" void kernel_launch(void* const* d_in, const int* in_sizes, int n_in,
                              void* d_out, int out_size) {
    const float4* pred = (const float4*)d_in[0];   // prediction_probs
    const float4* expo = (const float4*)d_in[1];   // expected_onehot
    float* out = (float*)d_out;

    bbox_kernel<<<BB, 1024>>>(pred, expo, out);
}